// round 12
// baseline (speedup 1.0000x reference)
#include <cuda_runtime.h>
#include <cuda_bf16.h>
#include <mma.h>

using namespace nvcuda;

#define NB    2048
#define NPH   10
#define NN    (NB*NPH)      // 20480
#define HD    128
#define NHEADS 4
#define NL    2
#define CDIM  32
#define FDIM  128
#define PCOLS 1536
// packed column offsets:
//   [0,512)      GAT xl
//   [512,1024)   GAT xr
//   [1024,1152)  CG fs
//   [1152,1280)  CG ss
//   [1280,1408)  CG fd
//   [1408,1536)  CG sd

// ---------------------------------------------------------------------------
// Scratch
// ---------------------------------------------------------------------------
__device__ float g_X  [2*NN*HD];
__device__ float g_PM [NN*PCOLS];
__device__ float g_PO [NN*PCOLS];
__device__ float g_WPM[NL*HD*PCOLS];   // tf32-rounded
__device__ float g_WPO[NL*HD*PCOLS];   // tf32-rounded
__device__ float g_WNT[NL*HD*HD];      // tf32-rounded node weights, TRANSPOSED [c][k]

// ---------------------------------------------------------------------------
// cp.async helpers
// ---------------------------------------------------------------------------
__device__ __forceinline__ void cp_async16(void* smem_dst, const void* gmem_src) {
    unsigned saddr = (unsigned)__cvta_generic_to_shared(smem_dst);
    asm volatile("cp.async.ca.shared.global [%0], [%1], 16;\n" :: "r"(saddr), "l"(gmem_src));
}
__device__ __forceinline__ void cp_commit() {
    asm volatile("cp.async.commit_group;\n");
}
template<int N> __device__ __forceinline__ void cp_wait() {
    asm volatile("cp.async.wait_group %0;\n" :: "n"(N));
}

// ---------------------------------------------------------------------------
// Weight packing (weights pre-rounded to tf32)
// ---------------------------------------------------------------------------
__global__ void pack_kernel(const float* __restrict__ gbWl, const float* __restrict__ gbWr,
                            const float* __restrict__ grWl, const float* __restrict__ grWr,
                            const float* __restrict__ clWf, const float* __restrict__ clWs,
                            const float* __restrict__ crWf, const float* __restrict__ crWs)
{
    int idx = blockIdx.x * blockDim.x + threadIdx.x;
    const int total = NL * HD * PCOLS;
    if (idx >= total) return;
    int l   = idx / (HD * PCOLS);
    int rem = idx - l * (HD * PCOLS);
    int k   = rem / PCOLS;
    int col = rem - k * PCOLS;
    float vm, vo;
    if (col < 512) {
        vm = gbWl[(l*HD + k)*512 + col];
        vo = grWl[(l*HD + k)*512 + col];
    } else if (col < 1024) {
        int c = col - 512;
        vm = grWr[(l*HD + k)*512 + c];
        vo = gbWr[(l*HD + k)*512 + c];
    } else if (col < 1152) {
        int c = col - 1024;
        vm = clWf[(l*2*HD + HD + k)*HD + c];
        vo = crWf[(l*2*HD + HD + k)*HD + c];
    } else if (col < 1280) {
        int c = col - 1152;
        vm = clWs[(l*2*HD + HD + k)*HD + c];
        vo = crWs[(l*2*HD + HD + k)*HD + c];
    } else if (col < 1408) {
        int c = col - 1280;
        vm = crWf[(l*2*HD + k)*HD + c];
        vo = clWf[(l*2*HD + k)*HD + c];
    } else {
        int c = col - 1408;
        vm = crWs[(l*2*HD + k)*HD + c];
        vo = clWs[(l*2*HD + k)*HD + c];
    }
    g_WPM[idx] = wmma::__float_to_tf32(vm);
    g_WPO[idx] = wmma::__float_to_tf32(vo);
}

// node weights: rounded + transposed to [l][c][k]
__global__ void pack_node_kernel(const float* __restrict__ nodeW)
{
    int idx = blockIdx.x * blockDim.x + threadIdx.x;
    if (idx >= NL*HD*HD) return;
    int l = idx / (HD*HD);
    int rem = idx - l*(HD*HD);
    int k = rem >> 7, c = rem & 127;
    g_WNT[l*HD*HD + c*HD + k] = wmma::__float_to_tf32(nodeW[idx]);
}

// ---------------------------------------------------------------------------
// Encoder (writes tf32-rounded X)
// ---------------------------------------------------------------------------
__global__ void encoder_kernel(const float* __restrict__ x_my, const float* __restrict__ x_opp,
                               const float* __restrict__ W, const float* __restrict__ b,
                               float* __restrict__ X)
{
    int idx = blockIdx.x * blockDim.x + threadIdx.x;
    if (idx >= 2*NN*HD) return;
    int row = idx >> 7, c = idx & 127;
    const float* x = (row < NN) ? (x_my + (size_t)row*CDIM) : (x_opp + (size_t)(row-NN)*CDIM);
    float acc = b[c];
#pragma unroll
    for (int k = 0; k < CDIM; k++) acc += x[k] * W[k*HD + c];
    X[idx] = wmma::__float_to_tf32(acc);
}

// ---------------------------------------------------------------------------
// tf32 tensor-core GEMM (frozen: 4 warps, warp tile 64x64, BK=32, cp.async
// double-buffered; operands pre-rounded at producers — no converts in loop).
// ---------------------------------------------------------------------------
#define AS_STRIDE 36
#define BS_STRIDE 132
#define AS_STAGE  (128*AS_STRIDE)
#define BS_STAGE  (32*BS_STRIDE)
#define GEMM_SMEM ((2*AS_STAGE + 2*BS_STAGE)*4)  // 70656 B

__global__ __launch_bounds__(128) void tc_gemm(
    const float* __restrict__ A0, const float* __restrict__ A1,
    const float* __restrict__ W0, const float* __restrict__ W1,
    float* __restrict__ C0, float* __restrict__ C1,
    int M, int Nc, int K)
{
    const float* A = blockIdx.z ? A1 : A0;
    const float* W = blockIdx.z ? W1 : W0;
    float* C       = blockIdx.z ? C1 : C0;

    extern __shared__ float smem[];
    float* As = smem;                  // [2][128][36]
    float* Bs = smem + 2*AS_STAGE;     // [2][32][132]

    const int tid = threadIdx.x;
    const int bm = blockIdx.y * 128;
    const int bn = blockIdx.x * 128;
    const int warp = tid >> 5;
    const int wm = warp & 1;           // 64-row slab
    const int wn = warp >> 1;          // 64-col slab

    wmma::fragment<wmma::accumulator, 16, 16, 8, float> acc[4][4];
#pragma unroll
    for (int mi = 0; mi < 4; mi++)
#pragma unroll
        for (int ni = 0; ni < 4; ni++)
            wmma::fill_fragment(acc[mi][ni], 0.f);

    const int ar = tid >> 3, ac = (tid & 7) * 4;    // A: 16 rows/iter, 8 f4 per row
    const int br = tid >> 5, bc = (tid & 31) * 4;   // B: 4 rows/iter, 32 f4 per row

    auto load_stage = [&](int kt, int buf) {
        float* as = As + buf*AS_STAGE;
        float* bs = Bs + buf*BS_STAGE;
#pragma unroll
        for (int it = 0; it < 8; ++it) {
            int r  = ar + it*16;
            cp_async16(&as[r*AS_STRIDE + ac], A + (size_t)(bm + r)*K + kt + ac);
            int r2 = br + it*4;
            cp_async16(&bs[r2*BS_STRIDE + bc], W + (size_t)(kt + r2)*Nc + bn + bc);
        }
        cp_commit();
    };

    const int T = K >> 5;
    load_stage(0, 0);

    for (int t = 0; t < T; t++) {
        if (t + 1 < T) load_stage((t+1) << 5, (t+1) & 1);
        if (t + 1 < T) cp_wait<1>(); else cp_wait<0>();
        __syncthreads();

        const float* as = As + (t & 1)*AS_STAGE;
        const float* bs = Bs + (t & 1)*BS_STAGE;
#pragma unroll
        for (int ks = 0; ks < 32; ks += 8) {
            wmma::fragment<wmma::matrix_a, 16, 16, 8, wmma::precision::tf32,
                           wmma::row_major> a[4];
            wmma::fragment<wmma::matrix_b, 16, 16, 8, wmma::precision::tf32,
                           wmma::row_major> b[4];
#pragma unroll
            for (int mi = 0; mi < 4; mi++)
                wmma::load_matrix_sync(a[mi], &as[(wm*64 + mi*16)*AS_STRIDE + ks], AS_STRIDE);
#pragma unroll
            for (int ni = 0; ni < 4; ni++)
                wmma::load_matrix_sync(b[ni], &bs[ks*BS_STRIDE + wn*64 + ni*16], BS_STRIDE);
#pragma unroll
            for (int mi = 0; mi < 4; mi++)
#pragma unroll
                for (int ni = 0; ni < 4; ni++)
                    wmma::mma_sync(acc[mi][ni], a[mi], b[ni], acc[mi][ni]);
        }
        __syncthreads();
    }

#pragma unroll
    for (int mi = 0; mi < 4; mi++)
#pragma unroll
        for (int ni = 0; ni < 4; ni++)
            wmma::store_matrix_sync(
                C + (size_t)(bm + wm*64 + mi*16)*Nc + bn + wn*64 + ni*16,
                acc[mi][ni], Nc, wmma::mem_row_major);
}

// ---------------------------------------------------------------------------
// Fused per-graph edge kernel (GATv2 + CGConv + NODE LINEAR, dense 10x10).
// Edge out goes to smem; epilogue multiplies by transposed tf32 node weight
// (L1-cached LDG) + bias and writes tf32-rounded X directly. Node GEMM gone.
// ---------------------------------------------------------------------------
struct EdgeArgs {
    const float *xl, *xr, *fd, *fs, *sd, *ss, *xdst, *att, *b, *bf, *bs;
    const float *wnT, *nb;   // node weight [c][k] + node bias
    float* out;              // X rows of this (graph, type)
};

__device__ __forceinline__ float fast_rcp(float d) {
    float y = __uint_as_float(0x7EF311C3u - __float_as_uint(d));
    y = y * (2.f - d*y);
    y = y * (2.f - d*y);
    y = y * (2.f - d*y);
    return y;
}

__global__ __launch_bounds__(256, 4) void edge_kernel(EdgeArgs A0, EdgeArgs A1)
{
    const EdgeArgs& a = blockIdx.y ? A1 : A0;
    __shared__ float s_xl [NPH*512];   // GAT source projections   (20 KB)
    __shared__ float s_efs[NPH*128];   // exp(-fs_i)                (5 KB)
    __shared__ float s_ess[NPH*128];   // exp(ss_i)                 (5 KB)
    __shared__ float s_ssr[NPH*128];   // raw ss_i                  (5 KB)
    __shared__ float s_al [NHEADS*NPH*NPH];                       // (1.6 KB)
    __shared__ float s_out[NPH*HD];    // pre-node edge output      (5 KB)

    const int g = blockIdx.x, t = threadIdx.x;
    const size_t base = (size_t)g * NPH;
    const int lane = t & 31, wid = t >> 5;

    for (int v = t; v < NPH*128; v += 256) {
        int r = v >> 7, c4 = (v & 127) * 4;
        *(float4*)&s_xl[r*512 + c4] = *(const float4*)(a.xl + (base + r)*PCOLS + c4);
    }
    for (int v = t; v < NPH*128; v += 256) {
        int r = v >> 7, c = v & 127;
        float fsv = a.fs[(base + r)*PCOLS + c];
        float ssv = a.ss[(base + r)*PCOLS + c];
        s_efs[v] = __expf(-fsv);
        s_ess[v] = __expf(ssv);
        s_ssr[v] = ssv;
    }
    __syncthreads();

    // GAT logits: warp per (h,j)
#pragma unroll
    for (int pp = 0; pp < 5; pp++) {
        int p = wid + pp*8;
        int h = p / 10, j = p - h*10;
        float4 xr4 = *(const float4*)(a.xr + (base + j)*PCOLS + h*128 + lane*4);
        float4 at4 = *(const float4*)(a.att + h*128 + lane*4);
        float lg[NPH];
#pragma unroll
        for (int i = 0; i < NPH; i++) {
            float4 xl4 = *(float4*)&s_xl[i*512 + h*128 + lane*4];
            float e0 = xl4.x + xr4.x; e0 = fmaxf(e0, 0.2f*e0);
            float e1 = xl4.y + xr4.y; e1 = fmaxf(e1, 0.2f*e1);
            float e2 = xl4.z + xr4.z; e2 = fmaxf(e2, 0.2f*e2);
            float e3 = xl4.w + xr4.w; e3 = fmaxf(e3, 0.2f*e3);
            lg[i] = e0*at4.x + e1*at4.y + e2*at4.z + e3*at4.w;
        }
#pragma unroll
        for (int o = 16; o; o >>= 1)
#pragma unroll
            for (int i = 0; i < NPH; i++) lg[i] += __shfl_xor_sync(0xffffffffu, lg[i], o);
        if (lane < NPH) s_al[h*100 + j*10 + lane] = lg[lane];
    }
    __syncthreads();

    if (t < NHEADS*NPH) {
        int h = t / 10, j = t - h*10;
        float* p = s_al + h*100 + j*10;
        float m = p[0];
#pragma unroll
        for (int i = 1; i < NPH; i++) m = fmaxf(m, p[i]);
        float ex[NPH]; float sum = 0.f;
#pragma unroll
        for (int i = 0; i < NPH; i++) { ex[i] = __expf(p[i] - m); sum += ex[i]; }
        float inv = __fdividef(1.f, sum + 1e-16f);
#pragma unroll
        for (int i = 0; i < NPH; i++) p[i] = ex[i] * inv;
    }
    __syncthreads();

    // edge output -> smem (reads xdst from global BEFORE epilogue overwrites it)
    for (int idx = t; idx < NPH*HD; idx += 256) {
        int j = idx >> 7, c = idx & 127;
        float gat = 0.f;
#pragma unroll
        for (int h = 0; h < NHEADS; h++) {
            const float* pal = s_al + h*100 + j*10;
            const float* pxl = s_xl + h*128 + c;
#pragma unroll
            for (int i = 0; i < NPH; i++) gat += pal[i] * pxl[i*512];
        }
        gat = 0.25f * gat + a.b[c];

        float fdv  = a.fd[(base + j)*PCOLS + c] + a.bf[c];
        float sdv  = a.sd[(base + j)*PCOLS + c] + a.bs[c];
        float efdn = __expf(-fdv);
        float esd  = __expf(sdv);

        float cg = 0.f;
#pragma unroll
        for (int i = 0; i < NPH; i++) {
            float xn  = fminf(efdn * s_efs[i*128 + c], 1e30f);
            float sig = fast_rcp(1.f + xn);
            float s   = sdv + s_ssr[i*128 + c];
            float es  = esd * s_ess[i*128 + c];
            float sp  = (s > 15.f) ? s : __logf(1.f + es);
            cg += sig * sp;
        }
        s_out[idx] = a.xdst[(base + j)*HD + c] + gat + cg;
    }
    __syncthreads();

    // fused node linear: X[j][c] = nb[c] + sum_k s_out[j][k] * wnT[c][k]
    {
        const int c = t & 127;
        const int jbase = (t >> 7) * 5;       // thread half -> j 0-4 or 5-9
        const float* wrow = a.wnT + c*HD;
        float accv[5];
        float nbv = a.nb[c];
#pragma unroll
        for (int j5 = 0; j5 < 5; j5++) accv[j5] = nbv;
#pragma unroll 4
        for (int q = 0; q < 32; q++) {
            float4 w4 = *(const float4*)(wrow + q*4);
#pragma unroll
            for (int j5 = 0; j5 < 5; j5++) {
                float4 o4 = *(const float4*)&s_out[(jbase + j5)*HD + q*4];
                accv[j5] += o4.x*w4.x + o4.y*w4.y + o4.z*w4.z + o4.w*w4.w;
            }
        }
#pragma unroll
        for (int j5 = 0; j5 < 5; j5++)
            a.out[(base + jbase + j5)*HD + c] = wmma::__float_to_tf32(accv[j5]);
    }
}

// ---------------------------------------------------------------------------
// Final head
// ---------------------------------------------------------------------------
__global__ __launch_bounds__(128) void final_kernel(
    const float* __restrict__ X, const float* __restrict__ W1,
    const float* __restrict__ b1, const float* __restrict__ W2,
    const float* __restrict__ b2, float* __restrict__ out)
{
    __shared__ float pool[2*HD];
    __shared__ float red[FDIM];
    const int g = blockIdx.x, t = threadIdx.x;
    const size_t base = (size_t)g * NPH;
    float pm = 0.f, po = 0.f;
#pragma unroll
    for (int r = 0; r < NPH; r++) {
        pm += X[(base + r)*HD + t];
        po += X[((size_t)NN + base + r)*HD + t];
    }
    pool[t]      = pm * 0.1f;
    pool[HD + t] = po * 0.1f;
    __syncthreads();
    float h = b1[t];
#pragma unroll 8
    for (int c = 0; c < 2*HD; c++) h += pool[c] * W1[c*FDIM + t];
    h = fminf(h, 128.f * h);
    red[t] = h * W2[t];
    __syncthreads();
    for (int s = 64; s > 0; s >>= 1) {
        if (t < s) red[t] += red[t + s];
        __syncthreads();
    }
    if (t == 0) out[g] = red[0] + b2[0];
}

// ---------------------------------------------------------------------------
// Launch
// ---------------------------------------------------------------------------
extern "C" void kernel_launch(void* const* d_in, const int* in_sizes, int n_in,
                              void* d_out, int out_size)
{
    const float* x_my  = (const float*)d_in[0];
    const float* x_opp = (const float*)d_in[1];
    const float* W_enc = (const float*)d_in[2];
    const float* b_enc = (const float*)d_in[3];
    const float* gbWl  = (const float*)d_in[4];
    const float* gbWr  = (const float*)d_in[5];
    const float* gbAtt = (const float*)d_in[6];
    const float* gbB   = (const float*)d_in[7];
    const float* grWl  = (const float*)d_in[8];
    const float* grWr  = (const float*)d_in[9];
    const float* grAtt = (const float*)d_in[10];
    const float* grB   = (const float*)d_in[11];
    const float* clWf  = (const float*)d_in[12];
    const float* clbf  = (const float*)d_in[13];
    const float* clWs  = (const float*)d_in[14];
    const float* clbs  = (const float*)d_in[15];
    const float* crWf  = (const float*)d_in[16];
    const float* crbf  = (const float*)d_in[17];
    const float* crWs  = (const float*)d_in[18];
    const float* crbs  = (const float*)d_in[19];
    const float* nodeW = (const float*)d_in[20];
    const float* nodeB = (const float*)d_in[21];
    const float* W1    = (const float*)d_in[22];
    const float* b1    = (const float*)d_in[23];
    const float* W2    = (const float*)d_in[24];
    const float* b2    = (const float*)d_in[25];
    float* out = (float*)d_out;

    float *X, *PM, *PO, *WPM, *WPO, *WNT;
    cudaGetSymbolAddress((void**)&X,   g_X);
    cudaGetSymbolAddress((void**)&PM,  g_PM);
    cudaGetSymbolAddress((void**)&PO,  g_PO);
    cudaGetSymbolAddress((void**)&WPM, g_WPM);
    cudaGetSymbolAddress((void**)&WPO, g_WPO);
    cudaGetSymbolAddress((void**)&WNT, g_WNT);

    cudaFuncSetAttribute(tc_gemm, cudaFuncAttributeMaxDynamicSharedMemorySize, GEMM_SMEM);

    {
        int total = NL * HD * PCOLS;
        pack_kernel<<<(total + 255)/256, 256>>>(gbWl, gbWr, grWl, grWr, clWf, clWs, crWf, crWs);
        pack_node_kernel<<<(NL*HD*HD + 255)/256, 256>>>(nodeW);
    }
    {
        int total = 2*NN*HD;
        encoder_kernel<<<(total + 255)/256, 256>>>(x_my, x_opp, W_enc, b_enc, X);
    }

    const size_t Wstep = (size_t)HD * PCOLS;
    for (int l = 0; l < NL; l++) {
        dim3 gP(PCOLS/128, NN/128, 2);
        tc_gemm<<<gP, 128, GEMM_SMEM>>>(X, X + (size_t)NN*HD,
                                        WPM + l*Wstep, WPO + l*Wstep,
                                        PM, PO, NN, PCOLS, HD);

        EdgeArgs eo; // new_xo = GAT(beats) + CG(loses), then node linear
        eo.xl = PM + 0;    eo.xr = PO + 512;
        eo.fd = PO + 1280; eo.fs = PM + 1024;
        eo.sd = PO + 1408; eo.ss = PM + 1152;
        eo.xdst = X + (size_t)NN*HD;
        eo.att = gbAtt + l*NHEADS*HD; eo.b = gbB + l*HD;
        eo.bf = clbf + l*HD; eo.bs = clbs + l*HD;
        eo.wnT = WNT + l*HD*HD; eo.nb = nodeB + l*HD;
        eo.out = X + (size_t)NN*HD;
        EdgeArgs em; // new_xm = CG(rev_beats) + GAT(rev_loses), then node linear
        em.xl = PO + 0;    em.xr = PM + 512;
        em.fd = PM + 1280; em.fs = PO + 1024;
        em.sd = PM + 1408; em.ss = PO + 1152;
        em.xdst = X;
        em.att = grAtt + l*NHEADS*HD; em.b = grB + l*HD;
        em.bf = crbf + l*HD; em.bs = crbs + l*HD;
        em.wnT = WNT + l*HD*HD; em.nb = nodeB + l*HD;
        em.out = X;
        edge_kernel<<<dim3(NB, 2), 256>>>(eo, em);
    }

    final_kernel<<<NB, 128>>>(X, W1, b1, W2, b2, out);
}

// round 13
// speedup vs baseline: 1.1736x; 1.1736x over previous
#include <cuda_runtime.h>
#include <cuda_bf16.h>
#include <mma.h>

using namespace nvcuda;

#define NB    2048
#define NPH   10
#define NN    (NB*NPH)      // 20480
#define HD    128
#define NHEADS 4
#define NL    2
#define CDIM  32
#define FDIM  128
#define PCOLS 1536
// packed column offsets:
//   [0,512)      GAT xl
//   [512,1024)   GAT xr
//   [1024,1152)  CG fs
//   [1152,1280)  CG ss
//   [1280,1408)  CG fd
//   [1408,1536)  CG sd

// ---------------------------------------------------------------------------
// Scratch
// ---------------------------------------------------------------------------
__device__ float g_X  [2*NN*HD];
__device__ float g_PM [NN*PCOLS];
__device__ float g_PO [NN*PCOLS];
__device__ float g_WPM[NL*HD*PCOLS];   // tf32-rounded
__device__ float g_WPO[NL*HD*PCOLS];   // tf32-rounded
__device__ float g_WN [NL*HD*HD];      // tf32-rounded node weights, ORIGINAL [k][c] layout

// ---------------------------------------------------------------------------
// cp.async helpers
// ---------------------------------------------------------------------------
__device__ __forceinline__ void cp_async16(void* smem_dst, const void* gmem_src) {
    unsigned saddr = (unsigned)__cvta_generic_to_shared(smem_dst);
    asm volatile("cp.async.ca.shared.global [%0], [%1], 16;\n" :: "r"(saddr), "l"(gmem_src));
}
__device__ __forceinline__ void cp_commit() {
    asm volatile("cp.async.commit_group;\n");
}
template<int N> __device__ __forceinline__ void cp_wait() {
    asm volatile("cp.async.wait_group %0;\n" :: "n"(N));
}

// ---------------------------------------------------------------------------
// Weight packing (weights pre-rounded to tf32)
// ---------------------------------------------------------------------------
__global__ void pack_kernel(const float* __restrict__ gbWl, const float* __restrict__ gbWr,
                            const float* __restrict__ grWl, const float* __restrict__ grWr,
                            const float* __restrict__ clWf, const float* __restrict__ clWs,
                            const float* __restrict__ crWf, const float* __restrict__ crWs)
{
    int idx = blockIdx.x * blockDim.x + threadIdx.x;
    const int total = NL * HD * PCOLS;
    if (idx >= total) return;
    int l   = idx / (HD * PCOLS);
    int rem = idx - l * (HD * PCOLS);
    int k   = rem / PCOLS;
    int col = rem - k * PCOLS;
    float vm, vo;
    if (col < 512) {
        vm = gbWl[(l*HD + k)*512 + col];
        vo = grWl[(l*HD + k)*512 + col];
    } else if (col < 1024) {
        int c = col - 512;
        vm = grWr[(l*HD + k)*512 + c];
        vo = gbWr[(l*HD + k)*512 + c];
    } else if (col < 1152) {
        int c = col - 1024;
        vm = clWf[(l*2*HD + HD + k)*HD + c];
        vo = crWf[(l*2*HD + HD + k)*HD + c];
    } else if (col < 1280) {
        int c = col - 1152;
        vm = clWs[(l*2*HD + HD + k)*HD + c];
        vo = crWs[(l*2*HD + HD + k)*HD + c];
    } else if (col < 1408) {
        int c = col - 1280;
        vm = crWf[(l*2*HD + k)*HD + c];
        vo = clWf[(l*2*HD + k)*HD + c];
    } else {
        int c = col - 1408;
        vm = crWs[(l*2*HD + k)*HD + c];
        vo = clWs[(l*2*HD + k)*HD + c];
    }
    g_WPM[idx] = wmma::__float_to_tf32(vm);
    g_WPO[idx] = wmma::__float_to_tf32(vo);
}

// node weights: rounded, ORIGINAL [l][k][c] layout (coalesced for lanes=c)
__global__ void pack_node_kernel(const float* __restrict__ nodeW)
{
    int idx = blockIdx.x * blockDim.x + threadIdx.x;
    if (idx >= NL*HD*HD) return;
    g_WN[idx] = wmma::__float_to_tf32(nodeW[idx]);
}

// ---------------------------------------------------------------------------
// Encoder
// ---------------------------------------------------------------------------
__global__ void encoder_kernel(const float* __restrict__ x_my, const float* __restrict__ x_opp,
                               const float* __restrict__ W, const float* __restrict__ b,
                               float* __restrict__ X)
{
    int idx = blockIdx.x * blockDim.x + threadIdx.x;
    if (idx >= 2*NN*HD) return;
    int row = idx >> 7, c = idx & 127;
    const float* x = (row < NN) ? (x_my + (size_t)row*CDIM) : (x_opp + (size_t)(row-NN)*CDIM);
    float acc = b[c];
#pragma unroll
    for (int k = 0; k < CDIM; k++) acc += x[k] * W[k*HD + c];
    X[idx] = acc;
}

// ---------------------------------------------------------------------------
// tf32 tensor-core GEMM (exact R8-measured config: 4 warps, warp tile 64x64,
// BK=32, cp.async double-buffered; B pre-rounded, A converted in-loop).
// ---------------------------------------------------------------------------
#define AS_STRIDE 36
#define BS_STRIDE 132
#define AS_STAGE  (128*AS_STRIDE)
#define BS_STAGE  (32*BS_STRIDE)
#define GEMM_SMEM ((2*AS_STAGE + 2*BS_STAGE)*4)  // 70656 B

__global__ __launch_bounds__(128) void tc_gemm(
    const float* __restrict__ A0, const float* __restrict__ A1,
    const float* __restrict__ W0, const float* __restrict__ W1,
    float* __restrict__ C0, float* __restrict__ C1,
    int M, int Nc, int K)
{
    const float* A = blockIdx.z ? A1 : A0;
    const float* W = blockIdx.z ? W1 : W0;
    float* C       = blockIdx.z ? C1 : C0;

    extern __shared__ float smem[];
    float* As = smem;                  // [2][128][36]
    float* Bs = smem + 2*AS_STAGE;     // [2][32][132]

    const int tid = threadIdx.x;
    const int bm = blockIdx.y * 128;
    const int bn = blockIdx.x * 128;
    const int warp = tid >> 5;
    const int wm = warp & 1;           // 64-row slab
    const int wn = warp >> 1;          // 64-col slab

    wmma::fragment<wmma::accumulator, 16, 16, 8, float> acc[4][4];
#pragma unroll
    for (int mi = 0; mi < 4; mi++)
#pragma unroll
        for (int ni = 0; ni < 4; ni++)
            wmma::fill_fragment(acc[mi][ni], 0.f);

    const int ar = tid >> 3, ac = (tid & 7) * 4;    // A: 16 rows/iter, 8 f4 per row
    const int br = tid >> 5, bc = (tid & 31) * 4;   // B: 4 rows/iter, 32 f4 per row

    auto load_stage = [&](int kt, int buf) {
        float* as = As + buf*AS_STAGE;
        float* bs = Bs + buf*BS_STAGE;
#pragma unroll
        for (int it = 0; it < 8; ++it) {
            int r  = ar + it*16;
            cp_async16(&as[r*AS_STRIDE + ac], A + (size_t)(bm + r)*K + kt + ac);
            int r2 = br + it*4;
            cp_async16(&bs[r2*BS_STRIDE + bc], W + (size_t)(kt + r2)*Nc + bn + bc);
        }
        cp_commit();
    };

    const int T = K >> 5;
    load_stage(0, 0);

    for (int t = 0; t < T; t++) {
        if (t + 1 < T) load_stage((t+1) << 5, (t+1) & 1);
        if (t + 1 < T) cp_wait<1>(); else cp_wait<0>();
        __syncthreads();

        const float* as = As + (t & 1)*AS_STAGE;
        const float* bs = Bs + (t & 1)*BS_STAGE;
#pragma unroll
        for (int ks = 0; ks < 32; ks += 8) {
            wmma::fragment<wmma::matrix_a, 16, 16, 8, wmma::precision::tf32,
                           wmma::row_major> a[4];
            wmma::fragment<wmma::matrix_b, 16, 16, 8, wmma::precision::tf32,
                           wmma::row_major> b[4];
#pragma unroll
            for (int mi = 0; mi < 4; mi++) {
                wmma::load_matrix_sync(a[mi], &as[(wm*64 + mi*16)*AS_STRIDE + ks], AS_STRIDE);
#pragma unroll
                for (int e = 0; e < a[mi].num_elements; e++)
                    a[mi].x[e] = wmma::__float_to_tf32(a[mi].x[e]);
            }
#pragma unroll
            for (int ni = 0; ni < 4; ni++)
                wmma::load_matrix_sync(b[ni], &bs[ks*BS_STRIDE + wn*64 + ni*16], BS_STRIDE);
#pragma unroll
            for (int mi = 0; mi < 4; mi++)
#pragma unroll
                for (int ni = 0; ni < 4; ni++)
                    wmma::mma_sync(acc[mi][ni], a[mi], b[ni], acc[mi][ni]);
        }
        __syncthreads();
    }

#pragma unroll
    for (int mi = 0; mi < 4; mi++)
#pragma unroll
        for (int ni = 0; ni < 4; ni++)
            wmma::store_matrix_sync(
                C + (size_t)(bm + wm*64 + mi*16)*Nc + bn + wn*64 + ni*16,
                acc[mi][ni], Nc, wmma::mem_row_major);
}

// ---------------------------------------------------------------------------
// Fused per-graph edge kernel (GATv2 + CGConv + NODE LINEAR, dense 10x10).
// R8 edge body; epilogue does node linear with weights in [k][c] layout:
// weight LDGs are lane-coalesced (lanes = consecutive c), s_out reads are
// warp-uniform smem broadcasts.
// ---------------------------------------------------------------------------
struct EdgeArgs {
    const float *xl, *xr, *fd, *fs, *sd, *ss, *xdst, *att, *b, *bf, *bs;
    const float *wn, *nb;    // node weight [k][c] + node bias
    float* out;              // X rows of this (graph, type)
};

__device__ __forceinline__ float fast_rcp(float d) {
    float y = __uint_as_float(0x7EF311C3u - __float_as_uint(d));
    y = y * (2.f - d*y);
    y = y * (2.f - d*y);
    y = y * (2.f - d*y);
    return y;
}

__global__ __launch_bounds__(256, 4) void edge_kernel(EdgeArgs A0, EdgeArgs A1)
{
    const EdgeArgs& a = blockIdx.y ? A1 : A0;
    __shared__ float s_xl [NPH*512];   // 20 KB
    __shared__ float s_efs[NPH*128];   // 5 KB
    __shared__ float s_ess[NPH*128];   // 5 KB
    __shared__ float s_ssr[NPH*128];   // 5 KB
    __shared__ float s_al [NHEADS*NPH*NPH];
    __shared__ float s_out[NPH*HD];    // 5 KB

    const int g = blockIdx.x, t = threadIdx.x;
    const size_t base = (size_t)g * NPH;
    const int lane = t & 31, wid = t >> 5;

    for (int v = t; v < NPH*128; v += 256) {
        int r = v >> 7, c4 = (v & 127) * 4;
        *(float4*)&s_xl[r*512 + c4] = *(const float4*)(a.xl + (base + r)*PCOLS + c4);
    }
    for (int v = t; v < NPH*128; v += 256) {
        int r = v >> 7, c = v & 127;
        float fsv = a.fs[(base + r)*PCOLS + c];
        float ssv = a.ss[(base + r)*PCOLS + c];
        s_efs[v] = __expf(-fsv);
        s_ess[v] = __expf(ssv);
        s_ssr[v] = ssv;
    }
    __syncthreads();

    // GAT logits: warp per (h,j)
#pragma unroll
    for (int pp = 0; pp < 5; pp++) {
        int p = wid + pp*8;
        int h = p / 10, j = p - h*10;
        float4 xr4 = *(const float4*)(a.xr + (base + j)*PCOLS + h*128 + lane*4);
        float4 at4 = *(const float4*)(a.att + h*128 + lane*4);
        float lg[NPH];
#pragma unroll
        for (int i = 0; i < NPH; i++) {
            float4 xl4 = *(float4*)&s_xl[i*512 + h*128 + lane*4];
            float e0 = xl4.x + xr4.x; e0 = fmaxf(e0, 0.2f*e0);
            float e1 = xl4.y + xr4.y; e1 = fmaxf(e1, 0.2f*e1);
            float e2 = xl4.z + xr4.z; e2 = fmaxf(e2, 0.2f*e2);
            float e3 = xl4.w + xr4.w; e3 = fmaxf(e3, 0.2f*e3);
            lg[i] = e0*at4.x + e1*at4.y + e2*at4.z + e3*at4.w;
        }
#pragma unroll
        for (int o = 16; o; o >>= 1)
#pragma unroll
            for (int i = 0; i < NPH; i++) lg[i] += __shfl_xor_sync(0xffffffffu, lg[i], o);
        if (lane < NPH) s_al[h*100 + j*10 + lane] = lg[lane];
    }
    __syncthreads();

    if (t < NHEADS*NPH) {
        int h = t / 10, j = t - h*10;
        float* p = s_al + h*100 + j*10;
        float m = p[0];
#pragma unroll
        for (int i = 1; i < NPH; i++) m = fmaxf(m, p[i]);
        float ex[NPH]; float sum = 0.f;
#pragma unroll
        for (int i = 0; i < NPH; i++) { ex[i] = __expf(p[i] - m); sum += ex[i]; }
        float inv = __fdividef(1.f, sum + 1e-16f);
#pragma unroll
        for (int i = 0; i < NPH; i++) p[i] = ex[i] * inv;
    }
    __syncthreads();

    // edge output -> smem (xdst read from global BEFORE epilogue overwrites it)
    for (int idx = t; idx < NPH*HD; idx += 256) {
        int j = idx >> 7, c = idx & 127;
        float gat = 0.f;
#pragma unroll
        for (int h = 0; h < NHEADS; h++) {
            const float* pal = s_al + h*100 + j*10;
            const float* pxl = s_xl + h*128 + c;
#pragma unroll
            for (int i = 0; i < NPH; i++) gat += pal[i] * pxl[i*512];
        }
        gat = 0.25f * gat + a.b[c];

        float fdv  = a.fd[(base + j)*PCOLS + c] + a.bf[c];
        float sdv  = a.sd[(base + j)*PCOLS + c] + a.bs[c];
        float efdn = __expf(-fdv);
        float esd  = __expf(sdv);

        float cg = 0.f;
#pragma unroll
        for (int i = 0; i < NPH; i++) {
            float xn  = fminf(efdn * s_efs[i*128 + c], 1e30f);
            float sig = fast_rcp(1.f + xn);
            float s   = sdv + s_ssr[i*128 + c];
            float es  = esd * s_ess[i*128 + c];
            float sp  = (s > 15.f) ? s : __logf(1.f + es);
            cg += sig * sp;
        }
        s_out[idx] = a.xdst[(base + j)*HD + c] + gat + cg;
    }
    __syncthreads();

    // fused node linear: X[j][c] = nb[c] + sum_k s_out[j][k] * wn[k][c]
    // lanes = consecutive c -> coalesced weight LDG; s_out reads broadcast.
    {
        const int c = t & 127;
        const int jbase = (t >> 7) * 5;       // thread half -> j 0-4 or 5-9
        float accv[5];
        float nbv = a.nb[c];
#pragma unroll
        for (int j5 = 0; j5 < 5; j5++) accv[j5] = nbv;
        const float* wp = a.wn + c;
#pragma unroll 8
        for (int k = 0; k < HD; k++) {
            float w = wp[k*HD];                // coalesced LDG.32
#pragma unroll
            for (int j5 = 0; j5 < 5; j5++)
                accv[j5] += s_out[(jbase + j5)*HD + k] * w;   // smem broadcast
        }
#pragma unroll
        for (int j5 = 0; j5 < 5; j5++)
            a.out[(base + jbase + j5)*HD + c] = accv[j5];
    }
}

// ---------------------------------------------------------------------------
// Final head
// ---------------------------------------------------------------------------
__global__ __launch_bounds__(128) void final_kernel(
    const float* __restrict__ X, const float* __restrict__ W1,
    const float* __restrict__ b1, const float* __restrict__ W2,
    const float* __restrict__ b2, float* __restrict__ out)
{
    __shared__ float pool[2*HD];
    __shared__ float red[FDIM];
    const int g = blockIdx.x, t = threadIdx.x;
    const size_t base = (size_t)g * NPH;
    float pm = 0.f, po = 0.f;
#pragma unroll
    for (int r = 0; r < NPH; r++) {
        pm += X[(base + r)*HD + t];
        po += X[((size_t)NN + base + r)*HD + t];
    }
    pool[t]      = pm * 0.1f;
    pool[HD + t] = po * 0.1f;
    __syncthreads();
    float h = b1[t];
#pragma unroll 8
    for (int c = 0; c < 2*HD; c++) h += pool[c] * W1[c*FDIM + t];
    h = fminf(h, 128.f * h);
    red[t] = h * W2[t];
    __syncthreads();
    for (int s = 64; s > 0; s >>= 1) {
        if (t < s) red[t] += red[t + s];
        __syncthreads();
    }
    if (t == 0) out[g] = red[0] + b2[0];
}

// ---------------------------------------------------------------------------
// Launch
// ---------------------------------------------------------------------------
extern "C" void kernel_launch(void* const* d_in, const int* in_sizes, int n_in,
                              void* d_out, int out_size)
{
    const float* x_my  = (const float*)d_in[0];
    const float* x_opp = (const float*)d_in[1];
    const float* W_enc = (const float*)d_in[2];
    const float* b_enc = (const float*)d_in[3];
    const float* gbWl  = (const float*)d_in[4];
    const float* gbWr  = (const float*)d_in[5];
    const float* gbAtt = (const float*)d_in[6];
    const float* gbB   = (const float*)d_in[7];
    const float* grWl  = (const float*)d_in[8];
    const float* grWr  = (const float*)d_in[9];
    const float* grAtt = (const float*)d_in[10];
    const float* grB   = (const float*)d_in[11];
    const float* clWf  = (const float*)d_in[12];
    const float* clbf  = (const float*)d_in[13];
    const float* clWs  = (const float*)d_in[14];
    const float* clbs  = (const float*)d_in[15];
    const float* crWf  = (const float*)d_in[16];
    const float* crbf  = (const float*)d_in[17];
    const float* crWs  = (const float*)d_in[18];
    const float* crbs  = (const float*)d_in[19];
    const float* nodeW = (const float*)d_in[20];
    const float* nodeB = (const float*)d_in[21];
    const float* W1    = (const float*)d_in[22];
    const float* b1    = (const float*)d_in[23];
    const float* W2    = (const float*)d_in[24];
    const float* b2    = (const float*)d_in[25];
    float* out = (float*)d_out;

    float *X, *PM, *PO, *WPM, *WPO, *WN;
    cudaGetSymbolAddress((void**)&X,   g_X);
    cudaGetSymbolAddress((void**)&PM,  g_PM);
    cudaGetSymbolAddress((void**)&PO,  g_PO);
    cudaGetSymbolAddress((void**)&WPM, g_WPM);
    cudaGetSymbolAddress((void**)&WPO, g_WPO);
    cudaGetSymbolAddress((void**)&WN,  g_WN);

    cudaFuncSetAttribute(tc_gemm, cudaFuncAttributeMaxDynamicSharedMemorySize, GEMM_SMEM);

    {
        int total = NL * HD * PCOLS;
        pack_kernel<<<(total + 255)/256, 256>>>(gbWl, gbWr, grWl, grWr, clWf, clWs, crWf, crWs);
        pack_node_kernel<<<(NL*HD*HD + 255)/256, 256>>>(nodeW);
    }
    {
        int total = 2*NN*HD;
        encoder_kernel<<<(total + 255)/256, 256>>>(x_my, x_opp, W_enc, b_enc, X);
    }

    const size_t Wstep = (size_t)HD * PCOLS;
    for (int l = 0; l < NL; l++) {
        dim3 gP(PCOLS/128, NN/128, 2);
        tc_gemm<<<gP, 128, GEMM_SMEM>>>(X, X + (size_t)NN*HD,
                                        WPM + l*Wstep, WPO + l*Wstep,
                                        PM, PO, NN, PCOLS, HD);

        EdgeArgs eo; // new_xo = GAT(beats) + CG(loses), then node linear
        eo.xl = PM + 0;    eo.xr = PO + 512;
        eo.fd = PO + 1280; eo.fs = PM + 1024;
        eo.sd = PO + 1408; eo.ss = PM + 1152;
        eo.xdst = X + (size_t)NN*HD;
        eo.att = gbAtt + l*NHEADS*HD; eo.b = gbB + l*HD;
        eo.bf = clbf + l*HD; eo.bs = clbs + l*HD;
        eo.wn = WN + l*HD*HD; eo.nb = nodeB + l*HD;
        eo.out = X + (size_t)NN*HD;
        EdgeArgs em; // new_xm = CG(rev_beats) + GAT(rev_loses), then node linear
        em.xl = PO + 0;    em.xr = PM + 512;
        em.fd = PM + 1280; em.fs = PO + 1024;
        em.sd = PM + 1408; em.ss = PO + 1152;
        em.xdst = X;
        em.att = grAtt + l*NHEADS*HD; em.b = grB + l*HD;
        em.bf = crbf + l*HD; em.bs = crbs + l*HD;
        em.wn = WN + l*HD*HD; em.nb = nodeB + l*HD;
        em.out = X;
        edge_kernel<<<dim3(NB, 2), 256>>>(eo, em);
    }

    final_kernel<<<NB, 128>>>(X, W1, b1, W2, b2, out);
}